// round 7
// baseline (speedup 1.0000x reference)
#include <cuda_runtime.h>

#define CHUNKS 16
#define RES_DIM 8192
#define NSE 1342177
#define BLOCKS_X 18               // partials per chunk; 18*16 = 288 blocks (2/SM)
#define TPB 1024

// Per-block partial accumulators: 16 chunks x 18 blocks x 8192 floats = 9.4 MB.
__device__ float g_part[CHUNKS * BLOCKS_X * RES_DIM];
// Global-atomic accumulator (L2-resident, 512 KB). Invariant: zero at
// kernel_launch entry (loader zero-init; finalize re-zeros after consuming).
__device__ float g_gacc[CHUNKS * RES_DIM];

// Kernel 1: COO scatter, dual-pipe accumulation.
// 6 of every 8 nnz -> smem atomics (on-SM MIO pipe), 2 of 8 -> global REDs
// (L2 atomic ALU). The two pipes run concurrently; per-pipe load matched to
// measured rates (smem ~326 ops/us, L2 ~134 ops/us chip-wide).
__global__ void __launch_bounds__(TPB, 2)
ptd_scatter_kernel(const float* __restrict__ vals,
                   const int*   __restrict__ rows,
                   const int*   __restrict__ cols,
                   const float* __restrict__ state) {
    __shared__ float sacc[RES_DIM];            // 32 KB private accumulator

    const int chunk = blockIdx.y;
    const size_t base = (size_t)chunk * NSE;
    const float* __restrict__ s = state + (size_t)chunk * RES_DIM;
    float* __restrict__ g = g_gacc + (size_t)chunk * RES_DIM;

    // Zero the private accumulator.
    {
        float4* s4 = reinterpret_cast<float4*>(sacc);
        #pragma unroll
        for (int i = threadIdx.x; i < RES_DIM / 4; i += TPB)
            s4[i] = make_float4(0.f, 0.f, 0.f, 0.f);
    }
    __syncthreads();

    // Alignment split (base not 16B-aligned since NSE is odd).
    const int head = (int)((4 - (base & 3)) & 3);
    const int nvec = (NSE - head) >> 2;
    const int tail = NSE - head - (nvec << 2);

    const float4* __restrict__ v4 = reinterpret_cast<const float4*>(vals + base + head);
    const int4*   __restrict__ r4 = reinterpret_cast<const int4*>(rows + base + head);
    const int4*   __restrict__ c4 = reinterpret_cast<const int4*>(cols + base + head);

    const int stride = BLOCKS_X * TPB;
    int i = blockIdx.x * TPB + threadIdx.x;

    // Main loop, unrolled x2 (8 nnz/thread/iter): 6 streaming LDG.128, then
    // 8 gathers; 6 smem atomics + 2 global REDs per iter.
    for (; i + stride < nvec; i += 2 * stride) {
        const int j = i + stride;
        float4 va = __ldcs(v4 + i); float4 vb = __ldcs(v4 + j);
        int4   ca = __ldcs(c4 + i); int4   cb = __ldcs(c4 + j);
        int4   ra = __ldcs(r4 + i); int4   rb = __ldcs(r4 + j);

        float fa0 = va.x * __ldg(s + ca.x), fa1 = va.y * __ldg(s + ca.y);
        float fa2 = va.z * __ldg(s + ca.z), fa3 = va.w * __ldg(s + ca.w);
        float fb0 = vb.x * __ldg(s + cb.x), fb1 = vb.y * __ldg(s + cb.y);
        float fb2 = vb.z * __ldg(s + cb.z), fb3 = vb.w * __ldg(s + cb.w);

        atomicAdd(g + ra.x,    fa0);   // L2 pipe
        atomicAdd(sacc + ra.y, fa1);
        atomicAdd(sacc + ra.z, fa2);
        atomicAdd(sacc + ra.w, fa3);
        atomicAdd(g + rb.x,    fb0);   // L2 pipe
        atomicAdd(sacc + rb.y, fb1);
        atomicAdd(sacc + rb.z, fb2);
        atomicAdd(sacc + rb.w, fb3);
    }
    for (; i < nvec; i += stride) {
        float4 va = __ldcs(v4 + i);
        int4   ca = __ldcs(c4 + i);
        int4   ra = __ldcs(r4 + i);
        atomicAdd(sacc + ra.x, va.x * __ldg(s + ca.x));
        atomicAdd(sacc + ra.y, va.y * __ldg(s + ca.y));
        atomicAdd(sacc + ra.z, va.z * __ldg(s + ca.z));
        atomicAdd(sacc + ra.w, va.w * __ldg(s + ca.w));
    }

    // Head + tail scalars (block x==0 only, into its own sacc).
    if (blockIdx.x == 0) {
        if (threadIdx.x < head) {
            const size_t k = base + threadIdx.x;
            atomicAdd(sacc + rows[k], vals[k] * __ldg(s + cols[k]));
        }
        if (threadIdx.x >= 32 && threadIdx.x < 32 + tail) {
            const size_t k = base + head + ((size_t)nvec << 2) + (threadIdx.x - 32);
            atomicAdd(sacc + rows[k], vals[k] * __ldg(s + cols[k]));
        }
    }
    __syncthreads();

    // Flush: plain vectorized stores to this block's scratch slice (2048 STG.128).
    {
        float4* dst = reinterpret_cast<float4*>(
            g_part + ((size_t)chunk * BLOCKS_X + blockIdx.x) * RES_DIM);
        const float4* src = reinterpret_cast<const float4*>(sacc);
        #pragma unroll
        for (int k = threadIdx.x; k < RES_DIM / 4; k += TPB)
            dst[k] = src[k];
    }
}

// Kernel 2: finalize.  out = taylor_tanh(proj + g_gacc + sum_b partials[b]).
// Also restores g_gacc to zero for the next launch (invariant).
__global__ void ptd_finalize_kernel(const float* __restrict__ proj,
                                    float* __restrict__ out) {
    int i = blockIdx.x * blockDim.x + threadIdx.x;       // float4 index
    if (i >= (CHUNKS * RES_DIM) / 4) return;

    const int chunk = i / (RES_DIM / 4);

    float4 z = reinterpret_cast<const float4*>(proj)[i];
    {
        float4 ga = reinterpret_cast<const float4*>(g_gacc)[i];
        z.x += ga.x; z.y += ga.y; z.z += ga.z; z.w += ga.w;
        reinterpret_cast<float4*>(g_gacc)[i] = make_float4(0.f, 0.f, 0.f, 0.f);
    }

    const float4* p4 = reinterpret_cast<const float4*>(
        g_part + (size_t)chunk * BLOCKS_X * RES_DIM);
    const int ofs = i - chunk * (RES_DIM / 4);           // float4 offset in chunk
    #pragma unroll
    for (int b = 0; b < BLOCKS_X; b++) {
        float4 p = __ldcs(p4 + (size_t)b * (RES_DIM / 4) + ofs);
        z.x += p.x; z.y += p.y; z.z += p.z; z.w += p.w;
    }

    const float t  = tanhf(1.6f);
    const float t2 = t * t;
    const float t3 = t2 * t;
    const float t4 = t2 * t2;
    const float t6 = t4 * t2;
    const float c0 = t;
    const float c1 = 1.0f - t2;
    const float c2 = t3 - t;
    const float c3 = -t4 + (4.0f / 3.0f) * t2 - (1.0f / 3.0f);
    const float c4 = (t / 3.0f) * (3.0f * t4 - 5.0f * t2 + 2.0f);
    const float c5 = -t6 + 2.0f * t4 - (17.0f / 15.0f) * t2 + (2.0f / 15.0f);

    float4 p;
    p.x = fmaf(z.x, fmaf(z.x, fmaf(z.x, fmaf(z.x, fmaf(z.x, c5, c4), c3), c2), c1), c0);
    p.y = fmaf(z.y, fmaf(z.y, fmaf(z.y, fmaf(z.y, fmaf(z.y, c5, c4), c3), c2), c1), c0);
    p.z = fmaf(z.z, fmaf(z.z, fmaf(z.z, fmaf(z.z, fmaf(z.z, c5, c4), c3), c2), c1), c0);
    p.w = fmaf(z.w, fmaf(z.w, fmaf(z.w, fmaf(z.w, fmaf(z.w, c5, c4), c3), c2), c1), c0);
    reinterpret_cast<float4*>(out)[i] = p;
}

extern "C" void kernel_launch(void* const* d_in, const int* in_sizes, int n_in,
                              void* d_out, int out_size) {
    const float* proj  = (const float*)d_in[0];
    const float* state = (const float*)d_in[1];
    const float* vals  = (const float*)d_in[2];
    const int*   rows  = (const int*)d_in[3];
    const int*   cols  = (const int*)d_in[4];
    float* out = (float*)d_out;

    {
        dim3 grid(BLOCKS_X, CHUNKS);   // 288 blocks x 1024 threads, 2/SM
        ptd_scatter_kernel<<<grid, TPB>>>(vals, rows, cols, state);
    }
    {
        int n4 = (CHUNKS * RES_DIM) / 4;
        ptd_finalize_kernel<<<(n4 + 255) / 256, 256>>>(proj, out);
    }
}

// round 8
// speedup vs baseline: 1.2876x; 1.2876x over previous
#include <cuda_runtime.h>

#define CHUNKS 16
#define RES_DIM 8192
#define NSE 1342177
#define BLOCKS_X 18               // partials per chunk; 18*16 = 288 blocks (2/SM)
#define TPB 1024
#define SMEM_BYTES (2 * RES_DIM * sizeof(float))   // sacc + sstate = 64 KB

// Per-block partial accumulators: 16 chunks x 18 blocks x 8192 floats = 9.4 MB.
__device__ float g_part[CHUNKS * BLOCKS_X * RES_DIM];

// Kernel 1: COO scatter with shared-memory privatization AND smem-staged state.
//  - sacc: private 32KB accumulator (smem atomics, no global atomics anywhere)
//  - sstate: 32KB copy of state[chunk] so the random gather is LDS
//    (~4 bank-conflict wavefronts/warp) instead of LDG (~28 sector
//    wavefronts/warp) -- the L1 data path was the measured bottleneck.
__global__ void __launch_bounds__(TPB, 2)
ptd_scatter_kernel(const float* __restrict__ vals,
                   const int*   __restrict__ rows,
                   const int*   __restrict__ cols,
                   const float* __restrict__ state) {
    extern __shared__ float smem[];
    float* sacc   = smem;             // [RES_DIM]
    float* sstate = smem + RES_DIM;   // [RES_DIM]

    const int chunk = blockIdx.y;
    const size_t base = (size_t)chunk * NSE;

    // Zero accumulator + stage state (both vectorized).
    {
        float4* a4 = reinterpret_cast<float4*>(sacc);
        float4* s4 = reinterpret_cast<float4*>(sstate);
        const float4* st4 = reinterpret_cast<const float4*>(state + (size_t)chunk * RES_DIM);
        #pragma unroll
        for (int i = threadIdx.x; i < RES_DIM / 4; i += TPB) {
            a4[i] = make_float4(0.f, 0.f, 0.f, 0.f);
            s4[i] = st4[i];
        }
    }
    __syncthreads();

    // Alignment split (base not 16B-aligned since NSE is odd).
    const int head = (int)((4 - (base & 3)) & 3);
    const int nvec = (NSE - head) >> 2;
    const int tail = NSE - head - (nvec << 2);

    const float4* __restrict__ v4 = reinterpret_cast<const float4*>(vals + base + head);
    const int4*   __restrict__ r4 = reinterpret_cast<const int4*>(rows + base + head);
    const int4*   __restrict__ c4 = reinterpret_cast<const int4*>(cols + base + head);

    const int stride = BLOCKS_X * TPB;
    int i = blockIdx.x * TPB + threadIdx.x;

    // Main loop, unrolled x2 (8 nnz/thread/iter): 6 streaming LDG.128, then
    // 8 LDS gathers and 8 smem atomics.
    for (; i + stride < nvec; i += 2 * stride) {
        const int j = i + stride;
        float4 va = __ldcs(v4 + i); float4 vb = __ldcs(v4 + j);
        int4   ca = __ldcs(c4 + i); int4   cb = __ldcs(c4 + j);
        int4   ra = __ldcs(r4 + i); int4   rb = __ldcs(r4 + j);

        float fa0 = va.x * sstate[ca.x], fa1 = va.y * sstate[ca.y];
        float fa2 = va.z * sstate[ca.z], fa3 = va.w * sstate[ca.w];
        float fb0 = vb.x * sstate[cb.x], fb1 = vb.y * sstate[cb.y];
        float fb2 = vb.z * sstate[cb.z], fb3 = vb.w * sstate[cb.w];

        atomicAdd(sacc + ra.x, fa0);
        atomicAdd(sacc + ra.y, fa1);
        atomicAdd(sacc + ra.z, fa2);
        atomicAdd(sacc + ra.w, fa3);
        atomicAdd(sacc + rb.x, fb0);
        atomicAdd(sacc + rb.y, fb1);
        atomicAdd(sacc + rb.z, fb2);
        atomicAdd(sacc + rb.w, fb3);
    }
    for (; i < nvec; i += stride) {
        float4 va = __ldcs(v4 + i);
        int4   ca = __ldcs(c4 + i);
        int4   ra = __ldcs(r4 + i);
        atomicAdd(sacc + ra.x, va.x * sstate[ca.x]);
        atomicAdd(sacc + ra.y, va.y * sstate[ca.y]);
        atomicAdd(sacc + ra.z, va.z * sstate[ca.z]);
        atomicAdd(sacc + ra.w, va.w * sstate[ca.w]);
    }

    // Head + tail scalars (block x==0 only, into its own sacc).
    if (blockIdx.x == 0) {
        if (threadIdx.x < head) {
            const size_t k = base + threadIdx.x;
            atomicAdd(sacc + rows[k], vals[k] * sstate[cols[k]]);
        }
        if (threadIdx.x >= 32 && threadIdx.x < 32 + tail) {
            const size_t k = base + head + ((size_t)nvec << 2) + (threadIdx.x - 32);
            atomicAdd(sacc + rows[k], vals[k] * sstate[cols[k]]);
        }
    }
    __syncthreads();

    // Flush: plain vectorized stores to this block's scratch slice (2048 STG.128).
    {
        float4* dst = reinterpret_cast<float4*>(
            g_part + ((size_t)chunk * BLOCKS_X + blockIdx.x) * RES_DIM);
        const float4* src = reinterpret_cast<const float4*>(sacc);
        #pragma unroll
        for (int k = threadIdx.x; k < RES_DIM / 4; k += TPB)
            dst[k] = src[k];
    }
}

// Kernel 2: finalize.  out = taylor_tanh(proj + sum_b partials[b]).
__global__ void ptd_finalize_kernel(const float* __restrict__ proj,
                                    float* __restrict__ out) {
    int i = blockIdx.x * blockDim.x + threadIdx.x;       // float4 index
    if (i >= (CHUNKS * RES_DIM) / 4) return;

    const int chunk = i / (RES_DIM / 4);

    float4 z = reinterpret_cast<const float4*>(proj)[i];

    const float4* p4 = reinterpret_cast<const float4*>(
        g_part + (size_t)chunk * BLOCKS_X * RES_DIM);
    const int ofs = i - chunk * (RES_DIM / 4);           // float4 offset in chunk
    #pragma unroll
    for (int b = 0; b < BLOCKS_X; b++) {
        float4 p = __ldcs(p4 + (size_t)b * (RES_DIM / 4) + ofs);
        z.x += p.x; z.y += p.y; z.z += p.z; z.w += p.w;
    }

    const float t  = tanhf(1.6f);
    const float t2 = t * t;
    const float t3 = t2 * t;
    const float t4 = t2 * t2;
    const float t6 = t4 * t2;
    const float c0 = t;
    const float c1 = 1.0f - t2;
    const float c2 = t3 - t;
    const float c3 = -t4 + (4.0f / 3.0f) * t2 - (1.0f / 3.0f);
    const float c4 = (t / 3.0f) * (3.0f * t4 - 5.0f * t2 + 2.0f);
    const float c5 = -t6 + 2.0f * t4 - (17.0f / 15.0f) * t2 + (2.0f / 15.0f);

    float4 p;
    p.x = fmaf(z.x, fmaf(z.x, fmaf(z.x, fmaf(z.x, fmaf(z.x, c5, c4), c3), c2), c1), c0);
    p.y = fmaf(z.y, fmaf(z.y, fmaf(z.y, fmaf(z.y, fmaf(z.y, c5, c4), c3), c2), c1), c0);
    p.z = fmaf(z.z, fmaf(z.z, fmaf(z.z, fmaf(z.z, fmaf(z.z, c5, c4), c3), c2), c1), c0);
    p.w = fmaf(z.w, fmaf(z.w, fmaf(z.w, fmaf(z.w, fmaf(z.w, c5, c4), c3), c2), c1), c0);
    reinterpret_cast<float4*>(out)[i] = p;
}

extern "C" void kernel_launch(void* const* d_in, const int* in_sizes, int n_in,
                              void* d_out, int out_size) {
    const float* proj  = (const float*)d_in[0];
    const float* state = (const float*)d_in[1];
    const float* vals  = (const float*)d_in[2];
    const int*   rows  = (const int*)d_in[3];
    const int*   cols  = (const int*)d_in[4];
    float* out = (float*)d_out;

    // 64 KB dynamic smem per block (static limit is 48 KB). Idempotent.
    cudaFuncSetAttribute(ptd_scatter_kernel,
                         cudaFuncAttributeMaxDynamicSharedMemorySize, SMEM_BYTES);

    {
        dim3 grid(BLOCKS_X, CHUNKS);   // 288 blocks x 1024 threads, 2/SM
        ptd_scatter_kernel<<<grid, TPB, SMEM_BYTES>>>(vals, rows, cols, state);
    }
    {
        int n4 = (CHUNKS * RES_DIM) / 4;
        ptd_finalize_kernel<<<(n4 + 255) / 256, 256>>>(proj, out);
    }
}

// round 10
// speedup vs baseline: 1.3035x; 1.0124x over previous
#include <cuda_runtime.h>

#define CHUNKS 16
#define RES_DIM 8192
#define NSE 1342177
#define BLOCKS_X 18               // partials per chunk; 18*16 = 288 blocks (2/SM)
#define TPB 1024
#define SMEM_BYTES (2 * RES_DIM * sizeof(float))   // sacc + sstate = 64 KB

// Per-block partial accumulators: 16 chunks x 18 blocks x 8192 floats = 9.4 MB.
__device__ float g_part[CHUNKS * BLOCKS_X * RES_DIM];

// Kernel 1: COO scatter with shared-memory privatization AND smem-staged state.
// Near the per-SM instruction-issue floor (~4 slots/nnz).
__global__ void __launch_bounds__(TPB, 2)
ptd_scatter_kernel(const float* __restrict__ vals,
                   const int*   __restrict__ rows,
                   const int*   __restrict__ cols,
                   const float* __restrict__ state) {
    extern __shared__ float smem[];
    float* sacc   = smem;             // [RES_DIM]
    float* sstate = smem + RES_DIM;   // [RES_DIM]

    const int chunk = blockIdx.y;
    const size_t base = (size_t)chunk * NSE;

    // Zero accumulator + stage state (both vectorized).
    {
        float4* a4 = reinterpret_cast<float4*>(sacc);
        float4* s4 = reinterpret_cast<float4*>(sstate);
        const float4* st4 = reinterpret_cast<const float4*>(state + (size_t)chunk * RES_DIM);
        #pragma unroll
        for (int i = threadIdx.x; i < RES_DIM / 4; i += TPB) {
            a4[i] = make_float4(0.f, 0.f, 0.f, 0.f);
            s4[i] = st4[i];
        }
    }
    __syncthreads();

    // Alignment split (base not 16B-aligned since NSE is odd).
    const int head = (int)((4 - (base & 3)) & 3);
    const int nvec = (NSE - head) >> 2;
    const int tail = NSE - head - (nvec << 2);

    const float4* __restrict__ v4 = reinterpret_cast<const float4*>(vals + base + head);
    const int4*   __restrict__ r4 = reinterpret_cast<const int4*>(rows + base + head);
    const int4*   __restrict__ c4 = reinterpret_cast<const int4*>(cols + base + head);

    const int stride = BLOCKS_X * TPB;
    int i = blockIdx.x * TPB + threadIdx.x;

    // Main loop, unrolled x2 (8 nnz/thread/iter).
    for (; i + stride < nvec; i += 2 * stride) {
        const int j = i + stride;
        float4 va = __ldcs(v4 + i); float4 vb = __ldcs(v4 + j);
        int4   ca = __ldcs(c4 + i); int4   cb = __ldcs(c4 + j);
        int4   ra = __ldcs(r4 + i); int4   rb = __ldcs(r4 + j);

        float fa0 = va.x * sstate[ca.x], fa1 = va.y * sstate[ca.y];
        float fa2 = va.z * sstate[ca.z], fa3 = va.w * sstate[ca.w];
        float fb0 = vb.x * sstate[cb.x], fb1 = vb.y * sstate[cb.y];
        float fb2 = vb.z * sstate[cb.z], fb3 = vb.w * sstate[cb.w];

        atomicAdd(sacc + ra.x, fa0);
        atomicAdd(sacc + ra.y, fa1);
        atomicAdd(sacc + ra.z, fa2);
        atomicAdd(sacc + ra.w, fa3);
        atomicAdd(sacc + rb.x, fb0);
        atomicAdd(sacc + rb.y, fb1);
        atomicAdd(sacc + rb.z, fb2);
        atomicAdd(sacc + rb.w, fb3);
    }
    for (; i < nvec; i += stride) {
        float4 va = __ldcs(v4 + i);
        int4   ca = __ldcs(c4 + i);
        int4   ra = __ldcs(r4 + i);
        atomicAdd(sacc + ra.x, va.x * sstate[ca.x]);
        atomicAdd(sacc + ra.y, va.y * sstate[ca.y]);
        atomicAdd(sacc + ra.z, va.z * sstate[ca.z]);
        atomicAdd(sacc + ra.w, va.w * sstate[ca.w]);
    }

    // Head + tail scalars (block x==0 only, into its own sacc).
    if (blockIdx.x == 0) {
        if (threadIdx.x < head) {
            const size_t k = base + threadIdx.x;
            atomicAdd(sacc + rows[k], vals[k] * sstate[cols[k]]);
        }
        if (threadIdx.x >= 32 && threadIdx.x < 32 + tail) {
            const size_t k = base + head + ((size_t)nvec << 2) + (threadIdx.x - 32);
            atomicAdd(sacc + rows[k], vals[k] * sstate[cols[k]]);
        }
    }
    __syncthreads();

    // Flush: plain vectorized stores to this block's scratch slice (2048 STG.128).
    {
        float4* dst = reinterpret_cast<float4*>(
            g_part + ((size_t)chunk * BLOCKS_X + blockIdx.x) * RES_DIM);
        const float4* src = reinterpret_cast<const float4*>(sacc);
        #pragma unroll
        for (int k = threadIdx.x; k < RES_DIM / 4; k += TPB)
            dst[k] = src[k];
    }
}

// Kernel 2: finalize.  out[i] = taylor_tanh(proj[i] + sum_b partials[b][i]).
// Scalarized: one thread per output float -> 131072 threads (4x the warps of
// the float4 version) to cover L2 latency; all loads coalesced; two
// independent accumulation chains to shorten the dependent-FADD tail.
__global__ void ptd_finalize_kernel(const float* __restrict__ proj,
                                    float* __restrict__ out) {
    const int i = blockIdx.x * blockDim.x + threadIdx.x;   // float index
    if (i >= CHUNKS * RES_DIM) return;

    const int chunk = i >> 13;                 // i / RES_DIM
    const int ofs   = i & (RES_DIM - 1);       // i % RES_DIM

    const float* __restrict__ p = g_part + (size_t)chunk * BLOCKS_X * RES_DIM + ofs;
    float z0 = proj[i];
    float z1 = 0.f;
    #pragma unroll
    for (int b = 0; b < BLOCKS_X; b += 2) {
        z0 += __ldcs(p + (size_t)b * RES_DIM);
        z1 += __ldcs(p + (size_t)(b + 1) * RES_DIM);
    }
    float z = z0 + z1;

    const float t  = tanhf(1.6f);
    const float t2 = t * t;
    const float t3 = t2 * t;
    const float t4 = t2 * t2;
    const float t6 = t4 * t2;
    const float c0 = t;
    const float c1 = 1.0f - t2;
    const float c2 = t3 - t;
    const float c3 = -t4 + (4.0f / 3.0f) * t2 - (1.0f / 3.0f);
    const float c4 = (t / 3.0f) * (3.0f * t4 - 5.0f * t2 + 2.0f);
    const float c5 = -t6 + 2.0f * t4 - (17.0f / 15.0f) * t2 + (2.0f / 15.0f);

    float r = fmaf(z, fmaf(z, fmaf(z, fmaf(z, fmaf(z, c5, c4), c3), c2), c1), c0);
    out[i] = r;
}

extern "C" void kernel_launch(void* const* d_in, const int* in_sizes, int n_in,
                              void* d_out, int out_size) {
    const float* proj  = (const float*)d_in[0];
    const float* state = (const float*)d_in[1];
    const float* vals  = (const float*)d_in[2];
    const int*   rows  = (const int*)d_in[3];
    const int*   cols  = (const int*)d_in[4];
    float* out = (float*)d_out;

    // 64 KB dynamic smem per block (static limit is 48 KB). Idempotent.
    cudaFuncSetAttribute(ptd_scatter_kernel,
                         cudaFuncAttributeMaxDynamicSharedMemorySize, SMEM_BYTES);

    {
        dim3 grid(BLOCKS_X, CHUNKS);   // 288 blocks x 1024 threads, 2/SM
        ptd_scatter_kernel<<<grid, TPB, SMEM_BYTES>>>(vals, rows, cols, state);
    }
    {
        int n = CHUNKS * RES_DIM;      // 131072 threads, one per output float
        ptd_finalize_kernel<<<(n + 255) / 256, 256>>>(proj, out);
    }
}